// round 6
// baseline (speedup 1.0000x reference)
#include <cuda_runtime.h>

// LIF spiking neuron: T=4, THRESH=1.0, TAU=1.0.
// x: [T=4, N=8388608] float32, out spikes: same shape float32.
// Per slot: mem += x[t]; spike = (mem > 1); mem = spike ? 0 : mem
//
// FINAL (roofline-converged): flat grid, block=256, 1 float4 per thread,
// all 4 timestep loads front-batched (MLP=4), streaming cache hints.
// 268 MB total traffic at ~7.5 TB/s effective = 94% of HBM spec.
// Probes that lost: 2x unroll (reg pressure -> occ 49%), grid-stride
// persistent (loop-serialized MLP), block=512 (neutral).

__global__ void __launch_bounds__(256) lif_spike_kernel(
    const float4* __restrict__ x,
    float4* __restrict__ out,
    int n4)   // number of float4 per timestep (2097152)
{
    int i = blockIdx.x * blockDim.x + threadIdx.x;
    if (i >= n4) return;

    // Front-batch the 4 independent timestep loads: MLP = 4.
    float4 x0 = __ldcs(x + i);
    float4 x1 = __ldcs(x + i + n4);
    float4 x2 = __ldcs(x + i + 2 * n4);
    float4 x3 = __ldcs(x + i + 3 * n4);

    float4 mem, s;

    // t = 0 (mem starts at 0, so mem = x0)
    mem = x0;
    s.x = (mem.x > 1.0f) ? 1.0f : 0.0f;
    s.y = (mem.y > 1.0f) ? 1.0f : 0.0f;
    s.z = (mem.z > 1.0f) ? 1.0f : 0.0f;
    s.w = (mem.w > 1.0f) ? 1.0f : 0.0f;
    __stcs(out + i, s);
    mem.x = (s.x > 0.f) ? 0.f : mem.x;
    mem.y = (s.y > 0.f) ? 0.f : mem.y;
    mem.z = (s.z > 0.f) ? 0.f : mem.z;
    mem.w = (s.w > 0.f) ? 0.f : mem.w;

    // t = 1
    mem.x += x1.x; mem.y += x1.y; mem.z += x1.z; mem.w += x1.w;
    s.x = (mem.x > 1.0f) ? 1.0f : 0.0f;
    s.y = (mem.y > 1.0f) ? 1.0f : 0.0f;
    s.z = (mem.z > 1.0f) ? 1.0f : 0.0f;
    s.w = (mem.w > 1.0f) ? 1.0f : 0.0f;
    __stcs(out + i + n4, s);
    mem.x = (s.x > 0.f) ? 0.f : mem.x;
    mem.y = (s.y > 0.f) ? 0.f : mem.y;
    mem.z = (s.z > 0.f) ? 0.f : mem.z;
    mem.w = (s.w > 0.f) ? 0.f : mem.w;

    // t = 2
    mem.x += x2.x; mem.y += x2.y; mem.z += x2.z; mem.w += x2.w;
    s.x = (mem.x > 1.0f) ? 1.0f : 0.0f;
    s.y = (mem.y > 1.0f) ? 1.0f : 0.0f;
    s.z = (mem.z > 1.0f) ? 1.0f : 0.0f;
    s.w = (mem.w > 1.0f) ? 1.0f : 0.0f;
    __stcs(out + i + 2 * n4, s);
    mem.x = (s.x > 0.f) ? 0.f : mem.x;
    mem.y = (s.y > 0.f) ? 0.f : mem.y;
    mem.z = (s.z > 0.f) ? 0.f : mem.z;
    mem.w = (s.w > 0.f) ? 0.f : mem.w;

    // t = 3 (no membrane update after last spike)
    mem.x += x3.x; mem.y += x3.y; mem.z += x3.z; mem.w += x3.w;
    s.x = (mem.x > 1.0f) ? 1.0f : 0.0f;
    s.y = (mem.y > 1.0f) ? 1.0f : 0.0f;
    s.z = (mem.z > 1.0f) ? 1.0f : 0.0f;
    s.w = (mem.w > 1.0f) ? 1.0f : 0.0f;
    __stcs(out + i + 3 * n4, s);
}

extern "C" void kernel_launch(void* const* d_in, const int* in_sizes, int n_in,
                              void* d_out, int out_size)
{
    const float4* x = (const float4*)d_in[0];
    float4* out = (float4*)d_out;

    int total = in_sizes[0];       // T * N floats
    int n_per_t = total / 4;       // floats per timestep
    int n4 = n_per_t / 4;          // float4 per timestep

    int threads = 256;
    int blocks = (n4 + threads - 1) / threads;
    lif_spike_kernel<<<blocks, threads>>>(x, out, n4);
}

// round 7
// speedup vs baseline: 1.0309x; 1.0309x over previous
#include <cuda_runtime.h>

// LIF spiking neuron: T=4, THRESH=1.0, TAU=1.0.
// x: [T=4, N=8388608] float32, out: same shape float32.
// Per slot: mem += x[t]; spike = (mem > 1); mem = spike ? 0 : mem
//
// R7 probe: 256-bit global accesses (ld/st.global.v8.f32, sm_100+).
// Each thread owns 8 consecutive floats per timestep. 2-deep load pipeline
// keeps bytes-in-flight equal to the best 128-bit kernel (64B/thread) while
// halving LDG/STG instruction count, without the R2 register blowup.

__device__ __forceinline__ void ldg256cs(const float* p, float* r) {
    asm volatile(
        "ld.global.cs.v8.f32 {%0,%1,%2,%3,%4,%5,%6,%7}, [%8];"
        : "=f"(r[0]), "=f"(r[1]), "=f"(r[2]), "=f"(r[3]),
          "=f"(r[4]), "=f"(r[5]), "=f"(r[6]), "=f"(r[7])
        : "l"(p));
}

__device__ __forceinline__ void stg256cs(float* p, const float* r) {
    asm volatile(
        "st.global.cs.v8.f32 [%0], {%1,%2,%3,%4,%5,%6,%7,%8};"
        :: "l"(p),
           "f"(r[0]), "f"(r[1]), "f"(r[2]), "f"(r[3]),
           "f"(r[4]), "f"(r[5]), "f"(r[6]), "f"(r[7])
        : "memory");
}

__global__ void __launch_bounds__(256) lif_spike_kernel(
    const float* __restrict__ x,
    float* __restrict__ out,
    int n)   // floats per timestep (8388608)
{
    long long idx = ((long long)blockIdx.x * blockDim.x + threadIdx.x) * 8;
    if (idx >= n) return;

    const float* xp = x + idx;
    float* op = out + idx;

    float a[8], b[8], mem[8], s[8];

    // Pipeline depth 2: t0 and t1 in flight before any compute.
    ldg256cs(xp, a);          // t0
    ldg256cs(xp + n, b);      // t1

    // t = 0 (mem starts at 0 -> mem = a)
    #pragma unroll
    for (int j = 0; j < 8; j++) {
        mem[j] = a[j];
        s[j] = (mem[j] > 1.0f) ? 1.0f : 0.0f;
    }
    stg256cs(op, s);
    #pragma unroll
    for (int j = 0; j < 8; j++)
        mem[j] = (s[j] > 0.0f) ? 0.0f : mem[j];

    ldg256cs(xp + 2LL * n, a);  // t2 (reuse a)

    // t = 1
    #pragma unroll
    for (int j = 0; j < 8; j++) {
        mem[j] += b[j];
        s[j] = (mem[j] > 1.0f) ? 1.0f : 0.0f;
    }
    stg256cs(op + n, s);
    #pragma unroll
    for (int j = 0; j < 8; j++)
        mem[j] = (s[j] > 0.0f) ? 0.0f : mem[j];

    ldg256cs(xp + 3LL * n, b);  // t3 (reuse b)

    // t = 2
    #pragma unroll
    for (int j = 0; j < 8; j++) {
        mem[j] += a[j];
        s[j] = (mem[j] > 1.0f) ? 1.0f : 0.0f;
    }
    stg256cs(op + 2LL * n, s);
    #pragma unroll
    for (int j = 0; j < 8; j++)
        mem[j] = (s[j] > 0.0f) ? 0.0f : mem[j];

    // t = 3 (no membrane update after last spike)
    #pragma unroll
    for (int j = 0; j < 8; j++) {
        mem[j] += b[j];
        s[j] = (mem[j] > 1.0f) ? 1.0f : 0.0f;
    }
    stg256cs(op + 3LL * n, s);
}

extern "C" void kernel_launch(void* const* d_in, const int* in_sizes, int n_in,
                              void* d_out, int out_size)
{
    const float* x = (const float*)d_in[0];
    float* out = (float*)d_out;

    int total = in_sizes[0];       // T * N floats
    int n = total / 4;             // floats per timestep

    int threads = 256;
    int elems_per_block = threads * 8;
    int blocks = (n + elems_per_block - 1) / elems_per_block;  // 4096
    lif_spike_kernel<<<blocks, threads>>>(x, out, n);
}